// round 4
// baseline (speedup 1.0000x reference)
#include <cuda_runtime.h>
#include <cstdint>
#include <cstddef>

#define VOCAB  32000
#define HIDDEN 1024
#define BATCH  8
#define SEQ    512
#define G4     (4*HIDDEN)       // 4096
#define MROWS  (BATCH*SEQ)      // 4096

// ---------------- static device scratch (no allocs allowed) ----------------
__device__ float g_emb[(size_t)MROWS * HIDDEN];          // 16.8 MB  [m][h], m = s*8+b
__device__ float g_xg [(size_t)MROWS * G4];              // 67 MB    [m][4H]
__device__ float g_hs [(size_t)MROWS * HIDDEN];          // 16.8 MB  [m][h]
__device__ float g_h  [2 * BATCH * HIDDEN];              // double-buffered h
__device__ float g_c  [BATCH * HIDDEN];
__device__ int   g_ids[MROWS];                           // decoded [b][s]

// ---------------- init: zero h, c ----------------
__global__ void init_state_kernel() {
    int i = blockIdx.x * 256 + threadIdx.x;
    if (i < 2 * BATCH * HIDDEN) g_h[i] = 0.f;
    if (i < BATCH * HIDDEN)     g_c[i] = 0.f;
}

// ---------------- dtype-agnostic id decode (int64 vs silently-downcast int32) ----
// If the buffer is little-endian int64 with ids < 2^31, every odd 32-bit word is 0.
// Detect that on the first 128 pairs; extract accordingly. Clamp into [0, VOCAB).
__global__ void decode_ids_kernel(const int* __restrict__ raw) {
    __shared__ int is64;
    if (threadIdx.x == 0) {
        int allzero = 1;
        for (int i = 0; i < 128; ++i)
            if (raw[2 * i + 1] != 0) { allzero = 0; break; }
        is64 = allzero;
    }
    __syncthreads();
    int i = blockIdx.x * 256 + threadIdx.x;
    if (i < MROWS) {
        int v = is64 ? raw[2 * i] : raw[i];
        if (v < 0) v = 0;
        if (v >= VOCAB) v = VOCAB - 1;
        g_ids[i] = v;
    }
}

// ---------------- embedding gather: emb[m][h] = W_out[h][ids[b][s]] ----------------
__global__ void gather_kernel(const float* __restrict__ Wout) {
    int idx = blockIdx.x * 256 + threadIdx.x;     // over MROWS*HIDDEN
    int m = idx >> 10;
    int h = idx & 1023;
    int b = m & 7, s = m >> 3;
    int id = g_ids[b * SEQ + s];
    g_emb[idx] = Wout[(size_t)h * VOCAB + (size_t)id];
}

// ---------------- 128x128x8 fp32 SGEMM, C = A*B + bias, optional row permute ----------------
// A: [M][K] row-major, B: [K][N] row-major. PERM=1 maps row m=s*8+b -> out row b*SEQ+s.
template <int PERM>
__global__ __launch_bounds__(256) void sgemm128(const float* __restrict__ A,
                                                const float* __restrict__ B,
                                                const float* __restrict__ bias,
                                                float* __restrict__ C,
                                                int M, int N, int K) {
    __shared__ float As[8][128];
    __shared__ float Bs[8][128];

    const int bx = blockIdx.x;          // N tile
    const int by = blockIdx.y;          // M tile
    const int tid = threadIdx.x;
    const int tx = tid & 15;
    const int ty = tid >> 4;

    const float* Aptr = A + (size_t)(by * 128) * K;
    const float* Bptr = B + (size_t)(bx * 128);

    const int arow = tid >> 1, acol = (tid & 1) * 4;
    const int brow = tid >> 5, bcol = (tid & 31) * 4;

    float acc[8][8];
#pragma unroll
    for (int i = 0; i < 8; ++i)
#pragma unroll
        for (int j = 0; j < 8; ++j) acc[i][j] = 0.f;

    for (int k0 = 0; k0 < K; k0 += 8) {
        float4 a4 = *(const float4*)(Aptr + (size_t)arow * K + k0 + acol);
        As[acol + 0][arow] = a4.x;
        As[acol + 1][arow] = a4.y;
        As[acol + 2][arow] = a4.z;
        As[acol + 3][arow] = a4.w;
        float4 b4 = *(const float4*)(Bptr + (size_t)(k0 + brow) * N + bcol);
        *(float4*)&Bs[brow][bcol] = b4;
        __syncthreads();

#pragma unroll
        for (int k = 0; k < 8; ++k) {
            float4 a0 = *(const float4*)&As[k][ty * 8];
            float4 a1 = *(const float4*)&As[k][ty * 8 + 4];
            float4 b0 = *(const float4*)&Bs[k][tx * 8];
            float4 b1 = *(const float4*)&Bs[k][tx * 8 + 4];
            float af[8] = {a0.x, a0.y, a0.z, a0.w, a1.x, a1.y, a1.z, a1.w};
            float bf[8] = {b0.x, b0.y, b0.z, b0.w, b1.x, b1.y, b1.z, b1.w};
#pragma unroll
            for (int i = 0; i < 8; ++i)
#pragma unroll
                for (int j = 0; j < 8; ++j)
                    acc[i][j] = fmaf(af[i], bf[j], acc[i][j]);
        }
        __syncthreads();
    }

    const int ncol0 = bx * 128 + tx * 8;
    float bv[8];
#pragma unroll
    for (int j = 0; j < 8; ++j) bv[j] = bias[ncol0 + j];

#pragma unroll
    for (int i = 0; i < 8; ++i) {
        int m = by * 128 + ty * 8 + i;
        size_t crow;
        if (PERM) crow = (size_t)((m & 7) * SEQ + (m >> 3));   // b*SEQ + s
        else      crow = (size_t)m;
        float* Cr = C + crow * (size_t)N + ncol0;
#pragma unroll
        for (int j = 0; j < 8; ++j) Cr[j] = acc[i][j] + bv[j];
    }
}

// ---------------- one LSTM timestep (fused gates GEMM + activations) ----------------
// grid 128 blocks (8 j-columns each), block 256 threads = (jl 0..7) x (gate 0..3) x (ks 0..7)
__global__ __launch_bounds__(256) void lstm_step_kernel(const float* __restrict__ Wh, int t) {
    __shared__ float h_s[BATCH * HIDDEN];          // 32 KB
    __shared__ float part[8][4][8][8];             // [ks][gate][jl][b]  8 KB

    const int tid = threadIdx.x;
    const float* __restrict__ hin  = g_h + (t & 1) * (BATCH * HIDDEN);
    float* __restrict__ hout       = g_h + ((t + 1) & 1) * (BATCH * HIDDEN);

    for (int i = tid; i < BATCH * HIDDEN; i += 256) h_s[i] = hin[i];
    __syncthreads();

    const int jl   = tid & 7;
    const int gate = (tid >> 3) & 3;
    const int ks   = tid >> 5;                      // 0..7, 128 k each
    const int j    = blockIdx.x * 8 + jl;
    const int col  = gate * HIDDEN + j;

    float acc[BATCH];
#pragma unroll
    for (int b = 0; b < BATCH; ++b) acc[b] = 0.f;

    const float* W = Wh + col;
    const int kbase = ks * 128;
#pragma unroll 8
    for (int ki = 0; ki < 128; ++ki) {
        int k = kbase + ki;
        float w = W[(size_t)k * G4];
#pragma unroll
        for (int b = 0; b < BATCH; ++b)
            acc[b] = fmaf(w, h_s[b * HIDDEN + k], acc[b]);
    }
#pragma unroll
    for (int b = 0; b < BATCH; ++b) part[ks][gate][jl][b] = acc[b];
    __syncthreads();

    if (tid < 64) {
        const int jl2 = tid & 7;
        const int b   = tid >> 3;
        const int j2  = blockIdx.x * 8 + jl2;
        float gsum[4];
#pragma unroll
        for (int g = 0; g < 4; ++g) {
            float s = 0.f;
#pragma unroll
            for (int k2 = 0; k2 < 8; ++k2) s += part[k2][g][jl2][b];
            gsum[g] = s + g_xg[((size_t)t * BATCH + b) * G4 + g * HIDDEN + j2];
        }
        float ig = 1.f / (1.f + expf(-gsum[0]));
        float fg = 1.f / (1.f + expf(-gsum[1]));
        float gg = tanhf(gsum[2]);
        float og = 1.f / (1.f + expf(-gsum[3]));
        float cn = fg * g_c[b * HIDDEN + j2] + ig * gg;
        g_c[b * HIDDEN + j2] = cn;
        float hn = og * tanhf(cn);
        hout[b * HIDDEN + j2] = hn;
        g_hs[((size_t)t * BATCH + b) * HIDDEN + j2] = hn;
    }
}

// ---------------- launch ----------------
extern "C" void kernel_launch(void* const* d_in, const int* in_sizes, int n_in,
                              void* d_out, int out_size) {
    const int*   ids_raw  = (const int*)d_in[0];         // [B][S] int64 or int32 (decoded on device)
    const float* W_out    = (const float*)d_in[1];       // [H][V]
    const float* b_out    = (const float*)d_in[2];       // [V]
    const float* Wx       = (const float*)d_in[3];       // [H][4H]
    const float* Wh       = (const float*)d_in[4];       // [H][4H]
    const float* b_lstm   = (const float*)d_in[5];       // [4H]
    float* out            = (float*)d_out;               // [B][S][V]

    void *p_emb, *p_xg, *p_hs;
    cudaGetSymbolAddress(&p_emb, g_emb);
    cudaGetSymbolAddress(&p_xg,  g_xg);
    cudaGetSymbolAddress(&p_hs,  g_hs);

    // 0) zero h, c; decode ids
    init_state_kernel<<<(2 * BATCH * HIDDEN + 255) / 256, 256>>>();
    decode_ids_kernel<<<(MROWS + 255) / 256, 256>>>(ids_raw);

    // 1) embedding gather
    gather_kernel<<<(MROWS * HIDDEN) / 256, 256>>>(W_out);

    // 2) x_gates = emb @ Wx + b_lstm   [4096 x 4096]
    {
        dim3 grid(G4 / 128, MROWS / 128);
        sgemm128<0><<<grid, 256>>>((const float*)p_emb, Wx, b_lstm, (float*)p_xg,
                                   MROWS, G4, HIDDEN);
    }

    // 3) recurrence: 512 sequential fused steps
    for (int t = 0; t < SEQ; ++t)
        lstm_step_kernel<<<128, 256>>>(Wh, t);

    // 4) logits = hs @ W_out + b_out, permuted to [B][S][V]
    {
        dim3 grid(VOCAB / 128, MROWS / 128);
        sgemm128<1><<<grid, 256>>>((const float*)p_hs, W_out, b_out, out,
                                   MROWS, VOCAB, HIDDEN);
    }
}

// round 5
// speedup vs baseline: 1.0074x; 1.0074x over previous
#include <cuda_runtime.h>
#include <cstdint>
#include <cstddef>

#define VOCAB  32000
#define HIDDEN 1024
#define BATCH  8
#define SEQ    512
#define G4     (4*HIDDEN)       // 4096
#define MROWS  (BATCH*SEQ)      // 4096

// ---------------- static device scratch (no allocs allowed) ----------------
__device__ float g_emb[(size_t)MROWS * HIDDEN];          // 16.8 MB  [m][h], m = s*8+b
__device__ float g_xg [(size_t)MROWS * G4];              // 67 MB    [m][4H]
__device__ float g_hs [(size_t)MROWS * HIDDEN];          // 16.8 MB  [m][h]
__device__ float g_WhT[(size_t)G4 * HIDDEN];             // 16.8 MB  [col][k]
__device__ float g_h  [2 * BATCH * HIDDEN];              // double-buffered h
__device__ float g_c  [BATCH * HIDDEN];
__device__ int   g_ids[MROWS];                           // decoded [b][s]

// ---------------- init: zero h, c ----------------
__global__ void init_state_kernel() {
    int i = blockIdx.x * 256 + threadIdx.x;
    if (i < 2 * BATCH * HIDDEN) g_h[i] = 0.f;
    if (i < BATCH * HIDDEN)     g_c[i] = 0.f;
}

// ---------------- dtype-agnostic id decode (int64 vs silently-downcast int32) ----
__global__ void decode_ids_kernel(const int* __restrict__ raw) {
    __shared__ int is64;
    if (threadIdx.x == 0) {
        int allzero = 1;
        for (int i = 0; i < 128; ++i)
            if (raw[2 * i + 1] != 0) { allzero = 0; break; }
        is64 = allzero;
    }
    __syncthreads();
    int i = blockIdx.x * 256 + threadIdx.x;
    if (i < MROWS) {
        int v = is64 ? raw[2 * i] : raw[i];
        if (v < 0) v = 0;
        if (v >= VOCAB) v = VOCAB - 1;
        g_ids[i] = v;
    }
}

// ---------------- embedding gather: emb[m][h] = W_out[h][ids[b][s]] ----------------
__global__ void gather_kernel(const float* __restrict__ Wout) {
    int idx = blockIdx.x * 256 + threadIdx.x;     // over MROWS*HIDDEN
    int m = idx >> 10;
    int h = idx & 1023;
    int b = m & 7, s = m >> 3;
    int id = g_ids[b * SEQ + s];
    g_emb[idx] = Wout[(size_t)h * VOCAB + (size_t)id];
}

// ---------------- Wh transpose: WhT[col][k] = Wh[k][col] ----------------
__global__ void transpose_wh_kernel(const float* __restrict__ Wh) {
    __shared__ float t[32][33];
    int bx = blockIdx.x;   // k tile  (32 tiles)
    int by = blockIdx.y;   // col tile (128 tiles)
    int x = threadIdx.x;   // 0..31
    int y = threadIdx.y;   // 0..7
#pragma unroll
    for (int i = 0; i < 4; ++i)
        t[y + i * 8][x] = Wh[(size_t)(bx * 32 + y + i * 8) * G4 + by * 32 + x];
    __syncthreads();
#pragma unroll
    for (int i = 0; i < 4; ++i)
        g_WhT[(size_t)(by * 32 + y + i * 8) * HIDDEN + bx * 32 + x] = t[x][y + i * 8];
}

// ---------------- 128x128x16 double-buffered fp32 SGEMM, C = A*B + bias ----------------
// A: [M][K] row-major, B: [K][N] row-major. PERM=1 maps row m=s*8+b -> out row b*SEQ+s.
template <int PERM>
__global__ __launch_bounds__(256, 2) void sgemm128(const float* __restrict__ A,
                                                   const float* __restrict__ B,
                                                   const float* __restrict__ bias,
                                                   float* __restrict__ C,
                                                   int M, int N, int K) {
    __shared__ float As[2][16][128];
    __shared__ float Bs[2][16][128];

    const int tid = threadIdx.x;
    const int bx = blockIdx.x;          // N tile
    const int by = blockIdx.y;          // M tile
    const int tx = tid & 15;
    const int ty = tid >> 4;

    const int arow = tid >> 1;          // 0..127
    const int acol = (tid & 1) * 8;     // 0 or 8
    const int brow = tid >> 5;          // 0..7
    const int bcol = (tid & 31) * 4;    // 0..124

    const float* Ab = A + (size_t)(by * 128 + arow) * K + acol;
    const float* Bb = B + (size_t)(bx * 128) + bcol;

    // prologue: load tile 0
    float4 a0r = *(const float4*)(Ab + 0);
    float4 a1r = *(const float4*)(Ab + 4);
    float4 b0r = *(const float4*)(Bb + (size_t)brow * N);
    float4 b1r = *(const float4*)(Bb + (size_t)(brow + 8) * N);

    As[0][acol + 0][arow] = a0r.x;  As[0][acol + 1][arow] = a0r.y;
    As[0][acol + 2][arow] = a0r.z;  As[0][acol + 3][arow] = a0r.w;
    As[0][acol + 4][arow] = a1r.x;  As[0][acol + 5][arow] = a1r.y;
    As[0][acol + 6][arow] = a1r.z;  As[0][acol + 7][arow] = a1r.w;
    *(float4*)&Bs[0][brow][bcol]     = b0r;
    *(float4*)&Bs[0][brow + 8][bcol] = b1r;
    __syncthreads();

    float acc[8][8];
#pragma unroll
    for (int i = 0; i < 8; ++i)
#pragma unroll
        for (int j = 0; j < 8; ++j) acc[i][j] = 0.f;

    int buf = 0;
    for (int k0 = 16; k0 < K; k0 += 16) {
        // prefetch next stage into registers (overlaps with compute below)
        a0r = *(const float4*)(Ab + k0);
        a1r = *(const float4*)(Ab + k0 + 4);
        b0r = *(const float4*)(Bb + (size_t)(k0 + brow) * N);
        b1r = *(const float4*)(Bb + (size_t)(k0 + brow + 8) * N);

#pragma unroll
        for (int k = 0; k < 16; ++k) {
            float4 A0 = *(const float4*)&As[buf][k][ty * 8];
            float4 A1 = *(const float4*)&As[buf][k][ty * 8 + 4];
            float4 B0 = *(const float4*)&Bs[buf][k][tx * 8];
            float4 B1 = *(const float4*)&Bs[buf][k][tx * 8 + 4];
            float af[8] = {A0.x, A0.y, A0.z, A0.w, A1.x, A1.y, A1.z, A1.w};
            float bf[8] = {B0.x, B0.y, B0.z, B0.w, B1.x, B1.y, B1.z, B1.w};
#pragma unroll
            for (int i = 0; i < 8; ++i)
#pragma unroll
                for (int j = 0; j < 8; ++j)
                    acc[i][j] = fmaf(af[i], bf[j], acc[i][j]);
        }

        // store prefetched stage into the other buffer
        int nb = buf ^ 1;
        As[nb][acol + 0][arow] = a0r.x;  As[nb][acol + 1][arow] = a0r.y;
        As[nb][acol + 2][arow] = a0r.z;  As[nb][acol + 3][arow] = a0r.w;
        As[nb][acol + 4][arow] = a1r.x;  As[nb][acol + 5][arow] = a1r.y;
        As[nb][acol + 6][arow] = a1r.z;  As[nb][acol + 7][arow] = a1r.w;
        *(float4*)&Bs[nb][brow][bcol]     = b0r;
        *(float4*)&Bs[nb][brow + 8][bcol] = b1r;
        __syncthreads();
        buf = nb;
    }

    // last stage
#pragma unroll
    for (int k = 0; k < 16; ++k) {
        float4 A0 = *(const float4*)&As[buf][k][ty * 8];
        float4 A1 = *(const float4*)&As[buf][k][ty * 8 + 4];
        float4 B0 = *(const float4*)&Bs[buf][k][tx * 8];
        float4 B1 = *(const float4*)&Bs[buf][k][tx * 8 + 4];
        float af[8] = {A0.x, A0.y, A0.z, A0.w, A1.x, A1.y, A1.z, A1.w};
        float bf[8] = {B0.x, B0.y, B0.z, B0.w, B1.x, B1.y, B1.z, B1.w};
#pragma unroll
        for (int i = 0; i < 8; ++i)
#pragma unroll
            for (int j = 0; j < 8; ++j)
                acc[i][j] = fmaf(af[i], bf[j], acc[i][j]);
    }

    const int ncol0 = bx * 128 + tx * 8;
    float bv[8];
#pragma unroll
    for (int j = 0; j < 8; ++j) bv[j] = bias[ncol0 + j];

#pragma unroll
    for (int i = 0; i < 8; ++i) {
        int m = by * 128 + ty * 8 + i;
        size_t crow;
        if (PERM) crow = (size_t)((m & 7) * SEQ + (m >> 3));   // b*SEQ + s
        else      crow = (size_t)m;
        float* Cr = C + crow * (size_t)N + ncol0;
#pragma unroll
        for (int j = 0; j < 8; ++j) Cr[j] = acc[i][j] + bv[j];
    }
}

// ---------------- one LSTM timestep (fused gates GEMM + activations) ----------------
// grid 256 blocks (4 j-columns each), 256 threads = (jl 0..3) x (gate 0..3) x (ks 0..15)
// Weights read from transposed WhT[col][k] -> contiguous float4 streams per thread.
__global__ __launch_bounds__(256) void lstm_step_kernel(int t) {
    __shared__ float h_s[BATCH * HIDDEN];          // 32 KB
    __shared__ float part[16][4][4][8];            // [ks][gate][jl][b]  8 KB

    const int tid = threadIdx.x;
    const float* __restrict__ hin  = g_h + (t & 1) * (BATCH * HIDDEN);
    float* __restrict__ hout       = g_h + ((t + 1) & 1) * (BATCH * HIDDEN);

    for (int i = tid; i < BATCH * HIDDEN; i += 256) h_s[i] = hin[i];
    __syncthreads();

    const int jl   = tid & 3;
    const int gate = (tid >> 2) & 3;
    const int ks   = tid >> 4;                      // 0..15, 64 k each
    const int j    = blockIdx.x * 4 + jl;
    const int col  = gate * HIDDEN + j;

    float acc[BATCH];
#pragma unroll
    for (int b = 0; b < BATCH; ++b) acc[b] = 0.f;

    const float4* __restrict__ Wp =
        (const float4*)(g_WhT + (size_t)col * HIDDEN) + ks * 16;

#pragma unroll
    for (int c = 0; c < 16; ++c) {
        float4 w = Wp[c];
        int k = ks * 64 + c * 4;
#pragma unroll
        for (int b = 0; b < BATCH; ++b) {
            float4 hv = *(const float4*)&h_s[b * HIDDEN + k];
            acc[b] += w.x * hv.x + w.y * hv.y + w.z * hv.z + w.w * hv.w;
        }
    }
#pragma unroll
    for (int b = 0; b < BATCH; ++b) part[ks][gate][jl][b] = acc[b];
    __syncthreads();

    if (tid < 32) {
        const int jl2 = tid & 3;
        const int b   = tid >> 2;
        const int j2  = blockIdx.x * 4 + jl2;
        float gsum[4];
#pragma unroll
        for (int g = 0; g < 4; ++g) {
            float s = 0.f;
#pragma unroll
            for (int k2 = 0; k2 < 16; ++k2) s += part[k2][g][jl2][b];
            gsum[g] = s + g_xg[((size_t)t * BATCH + b) * G4 + g * HIDDEN + j2];
        }
        float ig = 1.f / (1.f + expf(-gsum[0]));
        float fg = 1.f / (1.f + expf(-gsum[1]));
        float gg = tanhf(gsum[2]);
        float og = 1.f / (1.f + expf(-gsum[3]));
        float cn = fg * g_c[b * HIDDEN + j2] + ig * gg;
        g_c[b * HIDDEN + j2] = cn;
        float hn = og * tanhf(cn);
        hout[b * HIDDEN + j2] = hn;
        g_hs[((size_t)t * BATCH + b) * HIDDEN + j2] = hn;
    }
}

// ---------------- launch ----------------
extern "C" void kernel_launch(void* const* d_in, const int* in_sizes, int n_in,
                              void* d_out, int out_size) {
    const int*   ids_raw  = (const int*)d_in[0];         // [B][S] int64 or int32 (decoded on device)
    const float* W_out    = (const float*)d_in[1];       // [H][V]
    const float* b_out    = (const float*)d_in[2];       // [V]
    const float* Wx       = (const float*)d_in[3];       // [H][4H]
    const float* Wh       = (const float*)d_in[4];       // [H][4H]
    const float* b_lstm   = (const float*)d_in[5];       // [4H]
    float* out            = (float*)d_out;               // [B][S][V]

    void *p_emb, *p_xg, *p_hs;
    cudaGetSymbolAddress(&p_emb, g_emb);
    cudaGetSymbolAddress(&p_xg,  g_xg);
    cudaGetSymbolAddress(&p_hs,  g_hs);

    // 0) zero h, c; decode ids; transpose Wh
    init_state_kernel<<<(2 * BATCH * HIDDEN + 255) / 256, 256>>>();
    decode_ids_kernel<<<(MROWS + 255) / 256, 256>>>(ids_raw);
    {
        dim3 tg(HIDDEN / 32, G4 / 32);
        transpose_wh_kernel<<<tg, dim3(32, 8)>>>(Wh);
    }

    // 1) embedding gather
    gather_kernel<<<(MROWS * HIDDEN) / 256, 256>>>(W_out);

    // 2) x_gates = emb @ Wx + b_lstm   [4096 x 4096]
    {
        dim3 grid(G4 / 128, MROWS / 128);
        sgemm128<0><<<grid, 256>>>((const float*)p_emb, Wx, b_lstm, (float*)p_xg,
                                   MROWS, G4, HIDDEN);
    }

    // 3) recurrence: 512 sequential fused steps
    for (int t = 0; t < SEQ; ++t)
        lstm_step_kernel<<<256, 256>>>(t);

    // 4) logits = hs @ W_out + b_out, permuted to [B][S][V]
    {
        dim3 grid(VOCAB / 128, MROWS / 128);
        sgemm128<1><<<grid, 256>>>((const float*)p_hs, W_out, b_out, out,
                                   MROWS, VOCAB, HIDDEN);
    }
}

// round 9
// speedup vs baseline: 1.2758x; 1.2665x over previous
#include <cuda_runtime.h>
#include <cuda_bf16.h>
#include <cstdint>
#include <cstddef>

#define VOCAB  32000
#define HIDDEN 1024
#define BATCH  8
#define SEQ    512
#define G4     (4*HIDDEN)       // 4096
#define MROWS  (BATCH*SEQ)      // 4096

// ---------------- static device scratch (no allocs allowed) ----------------
__device__ float g_emb[(size_t)MROWS * HIDDEN];          // [m][h], m = s*8+b
__device__ float g_xg [(size_t)MROWS * G4];              // [m][4H]
__device__ float g_hs [(size_t)MROWS * HIDDEN];          // [m][h]
__device__ float g_WhT[(size_t)G4 * HIDDEN];             // [col][k]
__device__ float g_h  [2 * BATCH * HIDDEN];              // double-buffered h
__device__ float g_c  [BATCH * HIDDEN];
__device__ int   g_ids[MROWS];
// bf16 split operands for tensor-core logits GEMM
__device__ __nv_bfloat16 g_hs_hi[(size_t)MROWS * HIDDEN];   // [m][k]
__device__ __nv_bfloat16 g_hs_lo[(size_t)MROWS * HIDDEN];
__device__ __nv_bfloat16 g_WT_hi[(size_t)VOCAB * HIDDEN];   // [v][k]
__device__ __nv_bfloat16 g_WT_lo[(size_t)VOCAB * HIDDEN];

// ================= base-target tensor-core helpers =================
#define CP_ASYNC16(dst, src) \
    asm volatile("cp.async.cg.shared.global [%0], [%1], 16;" :: "r"(dst), "l"(src))
#define CP_COMMIT() asm volatile("cp.async.commit_group;" ::: "memory")
#define CP_WAIT(n)  asm volatile("cp.async.wait_group %0;" :: "n"(n) : "memory")

__device__ __forceinline__ uint32_t smem_u32(const void* p) {
    uint32_t a;
    asm("{ .reg .u64 t; cvta.to.shared.u64 t, %1; cvt.u32.u64 %0, t; }" : "=r"(a) : "l"(p));
    return a;
}
__device__ __forceinline__ void ldmx4(uint32_t* r, uint32_t addr) {
    asm volatile("ldmatrix.sync.aligned.m8n8.x4.shared.b16 {%0,%1,%2,%3}, [%4];"
                 : "=r"(r[0]), "=r"(r[1]), "=r"(r[2]), "=r"(r[3]) : "r"(addr));
}
__device__ __forceinline__ void mma16816(float* c, const uint32_t* a, const uint32_t* b) {
    asm volatile("mma.sync.aligned.m16n8k16.row.col.f32.bf16.bf16.f32 "
                 "{%0,%1,%2,%3}, {%4,%5,%6,%7}, {%8,%9}, {%0,%1,%2,%3};"
                 : "+f"(c[0]), "+f"(c[1]), "+f"(c[2]), "+f"(c[3])
                 : "r"(a[0]), "r"(a[1]), "r"(a[2]), "r"(a[3]), "r"(b[0]), "r"(b[1]));
}

// ---------------- init: zero h, c ----------------
__global__ void init_state_kernel() {
    int i = blockIdx.x * 256 + threadIdx.x;
    if (i < 2 * BATCH * HIDDEN) g_h[i] = 0.f;
    if (i < BATCH * HIDDEN)     g_c[i] = 0.f;
}

// ---------------- dtype-agnostic id decode ----------------
__global__ void decode_ids_kernel(const int* __restrict__ raw) {
    __shared__ int is64;
    if (threadIdx.x == 0) {
        int allzero = 1;
        for (int i = 0; i < 128; ++i)
            if (raw[2 * i + 1] != 0) { allzero = 0; break; }
        is64 = allzero;
    }
    __syncthreads();
    int i = blockIdx.x * 256 + threadIdx.x;
    if (i < MROWS) {
        int v = is64 ? raw[2 * i] : raw[i];
        if (v < 0) v = 0;
        if (v >= VOCAB) v = VOCAB - 1;
        g_ids[i] = v;
    }
}

// ---------------- embedding gather ----------------
__global__ void gather_kernel(const float* __restrict__ Wout) {
    int idx = blockIdx.x * 256 + threadIdx.x;
    int m = idx >> 10;
    int h = idx & 1023;
    int b = m & 7, s = m >> 3;
    int id = g_ids[b * SEQ + s];
    g_emb[idx] = Wout[(size_t)h * VOCAB + (size_t)id];
}

// ---------------- Wh transpose ----------------
__global__ void transpose_wh_kernel(const float* __restrict__ Wh) {
    __shared__ float t[32][33];
    int bx = blockIdx.x, by = blockIdx.y;
    int x = threadIdx.x, y = threadIdx.y;
#pragma unroll
    for (int i = 0; i < 4; ++i)
        t[y + i * 8][x] = Wh[(size_t)(bx * 32 + y + i * 8) * G4 + by * 32 + x];
    __syncthreads();
#pragma unroll
    for (int i = 0; i < 4; ++i)
        g_WhT[(size_t)(by * 32 + y + i * 8) * HIDDEN + bx * 32 + x] = t[x][y + i * 8];
}

// ---------------- split hs -> bf16 hi/lo ----------------
__global__ void split_hs_kernel() {
    int i = (blockIdx.x * 256 + threadIdx.x) * 4;
    float4 v = *(const float4*)&g_hs[i];
    float vv[4] = {v.x, v.y, v.z, v.w};
#pragma unroll
    for (int j = 0; j < 4; ++j) {
        __nv_bfloat16 hi = __float2bfloat16(vv[j]);
        g_hs_hi[i + j] = hi;
        g_hs_lo[i + j] = __float2bfloat16(vv[j] - __bfloat162float(hi));
    }
}

// ---------------- W_out transpose + split: WT[v][k] bf16 hi/lo ----------------
__global__ void split_wout_kernel(const float* __restrict__ W) {
    __shared__ float t[32][33];
    int v0 = blockIdx.x * 32, k0 = blockIdx.y * 32;
    int x = threadIdx.x, y = threadIdx.y;
#pragma unroll
    for (int i = 0; i < 4; ++i)
        t[y + i * 8][x] = W[(size_t)(k0 + y + i * 8) * VOCAB + v0 + x];   // t[k][v]
    __syncthreads();
#pragma unroll
    for (int i = 0; i < 4; ++i) {
        float val = t[x][y + i * 8];
        __nv_bfloat16 hi = __float2bfloat16(val);
        size_t o = (size_t)(v0 + y + i * 8) * HIDDEN + k0 + x;
        g_WT_hi[o] = hi;
        g_WT_lo[o] = __float2bfloat16(val - __bfloat162float(hi));
    }
}

// ---------------- 128x128x16 double-buffered fp32 SGEMM (x_gates) ----------------
template <int PERM>
__global__ __launch_bounds__(256, 2) void sgemm128(const float* __restrict__ A,
                                                   const float* __restrict__ B,
                                                   const float* __restrict__ bias,
                                                   float* __restrict__ C,
                                                   int M, int N, int K) {
    __shared__ float As[2][16][128];
    __shared__ float Bs[2][16][128];

    const int tid = threadIdx.x;
    const int bx = blockIdx.x, by = blockIdx.y;
    const int tx = tid & 15, ty = tid >> 4;
    const int arow = tid >> 1, acol = (tid & 1) * 8;
    const int brow = tid >> 5, bcol = (tid & 31) * 4;

    const float* Ab = A + (size_t)(by * 128 + arow) * K + acol;
    const float* Bb = B + (size_t)(bx * 128) + bcol;

    float4 a0r = *(const float4*)(Ab + 0);
    float4 a1r = *(const float4*)(Ab + 4);
    float4 b0r = *(const float4*)(Bb + (size_t)brow * N);
    float4 b1r = *(const float4*)(Bb + (size_t)(brow + 8) * N);

    As[0][acol + 0][arow] = a0r.x;  As[0][acol + 1][arow] = a0r.y;
    As[0][acol + 2][arow] = a0r.z;  As[0][acol + 3][arow] = a0r.w;
    As[0][acol + 4][arow] = a1r.x;  As[0][acol + 5][arow] = a1r.y;
    As[0][acol + 6][arow] = a1r.z;  As[0][acol + 7][arow] = a1r.w;
    *(float4*)&Bs[0][brow][bcol]     = b0r;
    *(float4*)&Bs[0][brow + 8][bcol] = b1r;
    __syncthreads();

    float acc[8][8];
#pragma unroll
    for (int i = 0; i < 8; ++i)
#pragma unroll
        for (int j = 0; j < 8; ++j) acc[i][j] = 0.f;

    int buf = 0;
    for (int k0 = 16; k0 < K; k0 += 16) {
        a0r = *(const float4*)(Ab + k0);
        a1r = *(const float4*)(Ab + k0 + 4);
        b0r = *(const float4*)(Bb + (size_t)(k0 + brow) * N);
        b1r = *(const float4*)(Bb + (size_t)(k0 + brow + 8) * N);

#pragma unroll
        for (int k = 0; k < 16; ++k) {
            float4 A0 = *(const float4*)&As[buf][k][ty * 8];
            float4 A1 = *(const float4*)&As[buf][k][ty * 8 + 4];
            float4 B0 = *(const float4*)&Bs[buf][k][tx * 8];
            float4 B1 = *(const float4*)&Bs[buf][k][tx * 8 + 4];
            float af[8] = {A0.x, A0.y, A0.z, A0.w, A1.x, A1.y, A1.z, A1.w};
            float bf[8] = {B0.x, B0.y, B0.z, B0.w, B1.x, B1.y, B1.z, B1.w};
#pragma unroll
            for (int i = 0; i < 8; ++i)
#pragma unroll
                for (int j = 0; j < 8; ++j)
                    acc[i][j] = fmaf(af[i], bf[j], acc[i][j]);
        }

        int nb = buf ^ 1;
        As[nb][acol + 0][arow] = a0r.x;  As[nb][acol + 1][arow] = a0r.y;
        As[nb][acol + 2][arow] = a0r.z;  As[nb][acol + 3][arow] = a0r.w;
        As[nb][acol + 4][arow] = a1r.x;  As[nb][acol + 5][arow] = a1r.y;
        As[nb][acol + 6][arow] = a1r.z;  As[nb][acol + 7][arow] = a1r.w;
        *(float4*)&Bs[nb][brow][bcol]     = b0r;
        *(float4*)&Bs[nb][brow + 8][bcol] = b1r;
        __syncthreads();
        buf = nb;
    }

#pragma unroll
    for (int k = 0; k < 16; ++k) {
        float4 A0 = *(const float4*)&As[buf][k][ty * 8];
        float4 A1 = *(const float4*)&As[buf][k][ty * 8 + 4];
        float4 B0 = *(const float4*)&Bs[buf][k][tx * 8];
        float4 B1 = *(const float4*)&Bs[buf][k][tx * 8 + 4];
        float af[8] = {A0.x, A0.y, A0.z, A0.w, A1.x, A1.y, A1.z, A1.w};
        float bf[8] = {B0.x, B0.y, B0.z, B0.w, B1.x, B1.y, B1.z, B1.w};
#pragma unroll
        for (int i = 0; i < 8; ++i)
#pragma unroll
            for (int j = 0; j < 8; ++j)
                acc[i][j] = fmaf(af[i], bf[j], acc[i][j]);
    }

    const int ncol0 = bx * 128 + tx * 8;
    float bv[8];
#pragma unroll
    for (int j = 0; j < 8; ++j) bv[j] = bias[ncol0 + j];

#pragma unroll
    for (int i = 0; i < 8; ++i) {
        int m = by * 128 + ty * 8 + i;
        size_t crow;
        if (PERM) crow = (size_t)((m & 7) * SEQ + (m >> 3));
        else      crow = (size_t)m;
        float* Cr = C + crow * (size_t)N + ncol0;
#pragma unroll
        for (int j = 0; j < 8; ++j) Cr[j] = acc[i][j] + bv[j];
    }
}

// ---------------- one LSTM timestep ----------------
__global__ __launch_bounds__(256) void lstm_step_kernel(int t) {
    __shared__ float h_s[BATCH * HIDDEN];
    __shared__ float part[16][4][4][8];

    const int tid = threadIdx.x;
    const float* __restrict__ hin  = g_h + (t & 1) * (BATCH * HIDDEN);
    float* __restrict__ hout       = g_h + ((t + 1) & 1) * (BATCH * HIDDEN);

    for (int i = tid; i < BATCH * HIDDEN; i += 256) h_s[i] = hin[i];
    __syncthreads();

    const int jl   = tid & 3;
    const int gate = (tid >> 2) & 3;
    const int ks   = tid >> 4;
    const int j    = blockIdx.x * 4 + jl;
    const int col  = gate * HIDDEN + j;

    float acc[BATCH];
#pragma unroll
    for (int b = 0; b < BATCH; ++b) acc[b] = 0.f;

    const float4* __restrict__ Wp =
        (const float4*)(g_WhT + (size_t)col * HIDDEN) + ks * 16;

#pragma unroll
    for (int c = 0; c < 16; ++c) {
        float4 w = Wp[c];
        int k = ks * 64 + c * 4;
#pragma unroll
        for (int b = 0; b < BATCH; ++b) {
            float4 hv = *(const float4*)&h_s[b * HIDDEN + k];
            acc[b] += w.x * hv.x + w.y * hv.y + w.z * hv.z + w.w * hv.w;
        }
    }
#pragma unroll
    for (int b = 0; b < BATCH; ++b) part[ks][gate][jl][b] = acc[b];
    __syncthreads();

    if (tid < 32) {
        const int jl2 = tid & 3;
        const int b   = tid >> 2;
        const int j2  = blockIdx.x * 4 + jl2;
        float gsum[4];
#pragma unroll
        for (int g = 0; g < 4; ++g) {
            float s = 0.f;
#pragma unroll
            for (int k2 = 0; k2 < 16; ++k2) s += part[k2][g][jl2][b];
            gsum[g] = s + g_xg[((size_t)t * BATCH + b) * G4 + g * HIDDEN + j2];
        }
        float ig = 1.f / (1.f + expf(-gsum[0]));
        float fg = 1.f / (1.f + expf(-gsum[1]));
        float gg = tanhf(gsum[2]);
        float og = 1.f / (1.f + expf(-gsum[3]));
        float cn = fg * g_c[b * HIDDEN + j2] + ig * gg;
        g_c[b * HIDDEN + j2] = cn;
        float hn = og * tanhf(cn);
        hout[b * HIDDEN + j2] = hn;
        g_hs[((size_t)t * BATCH + b) * HIDDEN + j2] = hn;
    }
}

// ================= mma.sync bf16-split logits GEMM =================
// CTA tile 128x128, 8 warps (2 M x 4 N), warp tile 64x32, m16n8k16 HMMA.
// 3 products: Ahi*Bhi + Ahi*Blo + Alo*Bhi over K=1024, BK=32, cp.async 2-stage.
#define L_STRIDE  80                       // bytes per smem row (32 bf16 + 16B pad)
#define L_AB      (128 * L_STRIDE)         // 10240 bytes per tile
#define L_STAGE   (2 * L_AB)               // A + B per stage
#define L_NIT     96                       // 3 products x 32 k-chunks

__global__ __launch_bounds__(256) void logits_mma_kernel(float* __restrict__ out,
                                                         const float* __restrict__ bias) {
    __shared__ char smem[2 * L_STAGE];     // 40 KB
    const uint32_t sbase = smem_u32(smem);

    const int tid  = threadIdx.x;
    const int lane = tid & 31;
    const int wid  = tid >> 5;
    const int wm   = wid >> 2;             // 0..1
    const int wn   = wid & 3;              // 0..3
    const int m0   = blockIdx.x * 128;
    const int n0   = blockIdx.y * 128;

    const int lrow = tid >> 2;             // 0..63
    const int lch  = tid & 3;              // 16B chunk

    float acc[4][4][4];
#pragma unroll
    for (int i = 0; i < 4; ++i)
#pragma unroll
        for (int j = 0; j < 4; ++j)
#pragma unroll
            for (int k = 0; k < 4; ++k) acc[i][j][k] = 0.f;

    // stage loader: product p (0:hi*hi 1:hi*lo 2:lo*hi), k-chunk kt, buffer s
    auto load_stage = [&](int it, int s) {
        const int p  = it >> 5;
        const int k0 = (it & 31) * 32;
        const __nv_bfloat16* Asrc = (p < 2) ? g_hs_hi : g_hs_lo;
        const __nv_bfloat16* Bsrc = (p == 1) ? g_WT_lo : g_WT_hi;
        uint32_t sa = sbase + s * L_STAGE;
        uint32_t sb = sa + L_AB;
#pragma unroll
        for (int rr = 0; rr < 128; rr += 64) {
            const __nv_bfloat16* srcA = Asrc + (size_t)(m0 + lrow + rr) * HIDDEN + k0 + lch * 8;
            CP_ASYNC16(sa + (lrow + rr) * L_STRIDE + lch * 16, srcA);
            const __nv_bfloat16* srcB = Bsrc + (size_t)(n0 + lrow + rr) * HIDDEN + k0 + lch * 8;
            CP_ASYNC16(sb + (lrow + rr) * L_STRIDE + lch * 16, srcB);
        }
        CP_COMMIT();
    };

    load_stage(0, 0);

    int buf = 0;
    for (int it = 0; it < L_NIT; ++it) {
        if (it + 1 < L_NIT) {
            load_stage(it + 1, buf ^ 1);
            CP_WAIT(1);
        } else {
            CP_WAIT(0);
        }
        __syncthreads();

        uint32_t sa = sbase + buf * L_STAGE;
        uint32_t sb = sa + L_AB;
#pragma unroll
        for (int k16 = 0; k16 < 2; ++k16) {
            const uint32_t koff = k16 * 32 + (lane >> 4) * 16;
            uint32_t a[4][4];
#pragma unroll
            for (int mf = 0; mf < 4; ++mf)
                ldmx4(a[mf], sa + (wm * 64 + mf * 16 + (lane & 15)) * L_STRIDE + koff);
            uint32_t bfr[4][2];
#pragma unroll
            for (int nh = 0; nh < 2; ++nh) {
                uint32_t t4[4];
                ldmx4(t4, sb + (wn * 32 + nh * 16 + (lane & 15)) * L_STRIDE + koff);
                bfr[nh * 2 + 0][0] = t4[0]; bfr[nh * 2 + 0][1] = t4[2];
                bfr[nh * 2 + 1][0] = t4[1]; bfr[nh * 2 + 1][1] = t4[3];
            }
#pragma unroll
            for (int mf = 0; mf < 4; ++mf)
#pragma unroll
                for (int nf = 0; nf < 4; ++nf)
                    mma16816(acc[mf][nf], a[mf], bfr[nf]);
        }
        __syncthreads();
        buf ^= 1;
    }

    // epilogue: bias + (b,s) permute.  c-frag: rows lane>>2 / +8, cols (lane&3)*2 +{0,1}
#pragma unroll
    for (int mf = 0; mf < 4; ++mf) {
        const int mbase = m0 + wm * 64 + mf * 16;
        const int m1 = mbase + (lane >> 2);
        const int m2 = m1 + 8;
        const size_t r1 = (size_t)((m1 & 7) * SEQ + (m1 >> 3)) * VOCAB;
        const size_t r2 = (size_t)((m2 & 7) * SEQ + (m2 >> 3)) * VOCAB;
#pragma unroll
        for (int nf = 0; nf < 4; ++nf) {
            const int n = n0 + wn * 32 + nf * 8 + (lane & 3) * 2;
            const float b0 = bias[n], b1 = bias[n + 1];
            float2 o1 = {acc[mf][nf][0] + b0, acc[mf][nf][1] + b1};
            float2 o2 = {acc[mf][nf][2] + b0, acc[mf][nf][3] + b1};
            *(float2*)(out + r1 + n) = o1;
            *(float2*)(out + r2 + n) = o2;
        }
    }
}

// ---------------- launch ----------------
extern "C" void kernel_launch(void* const* d_in, const int* in_sizes, int n_in,
                              void* d_out, int out_size) {
    const int*   ids_raw  = (const int*)d_in[0];
    const float* W_out    = (const float*)d_in[1];       // [H][V]
    const float* b_out    = (const float*)d_in[2];       // [V]
    const float* Wx       = (const float*)d_in[3];       // [H][4H]
    const float* Wh       = (const float*)d_in[4];       // [H][4H]
    const float* b_lstm   = (const float*)d_in[5];       // [4H]
    float* out            = (float*)d_out;               // [B][S][V]

    void *p_emb, *p_xg;
    cudaGetSymbolAddress(&p_emb, g_emb);
    cudaGetSymbolAddress(&p_xg,  g_xg);

    // 0) zero h, c; decode ids; transpose Wh; split W_out
    init_state_kernel<<<(2 * BATCH * HIDDEN + 255) / 256, 256>>>();
    decode_ids_kernel<<<(MROWS + 255) / 256, 256>>>(ids_raw);
    {
        dim3 tg(HIDDEN / 32, G4 / 32);
        transpose_wh_kernel<<<tg, dim3(32, 8)>>>(Wh);
    }
    {
        dim3 wg(VOCAB / 32, HIDDEN / 32);
        split_wout_kernel<<<wg, dim3(32, 8)>>>(W_out);
    }

    // 1) embedding gather
    gather_kernel<<<(MROWS * HIDDEN) / 256, 256>>>(W_out);

    // 2) x_gates = emb @ Wx + b_lstm
    {
        dim3 grid(G4 / 128, MROWS / 128);
        sgemm128<0><<<grid, 256>>>((const float*)p_emb, Wx, b_lstm, (float*)p_xg,
                                   MROWS, G4, HIDDEN);
    }

    // 3) recurrence
    for (int t = 0; t < SEQ; ++t)
        lstm_step_kernel<<<256, 256>>>(t);

    // 4) split hs to bf16 hi/lo
    split_hs_kernel<<<(MROWS * HIDDEN / 4) / 256, 256>>>();

    // 5) logits = hs @ W_out + b_out via mma.sync bf16 3-product split
    {
        dim3 grid(MROWS / 128, VOCAB / 128);
        logits_mma_kernel<<<grid, 256>>>(out, b_out);
    }
}